// round 15
// baseline (speedup 1.0000x reference)
#include <cuda_runtime.h>
#include <cuda_bf16.h>
#include <cstdint>

#define BB 2
#define SS 4096
#define DD 768
#define HH 12
#define HD 64
#define N3 (3*DD)
#define MM (BB*SS)

// bf16 hi/lo scratch
__device__ __align__(16) __nv_bfloat16 g_qh[BB*HH*SS*HD], g_ql[BB*HH*SS*HD];
__device__ __align__(16) __nv_bfloat16 g_kh[BB*HH*SS*HD], g_kl[BB*HH*SS*HD];
__device__ __align__(16) __nv_bfloat16 g_vh[BB*HH*SS*HD], g_vl[BB*HH*SS*HD];
__device__ __align__(16) __nv_bfloat16 g_oh[MM*DD],  g_ol[MM*DD];
__device__ __align__(16) __nv_bfloat16 g_xh[MM*DD],  g_xl[MM*DD];
__device__ __align__(16) __nv_bfloat16 g_w1h[N3*DD], g_w1l[N3*DD];
__device__ __align__(16) __nv_bfloat16 g_w2h[DD*DD], g_w2l[DD*DD];

// ---------------- helpers ----------------
__device__ __forceinline__ uint32_t smem_u32(const void* p) {
    uint32_t a;
    asm("{ .reg .u64 t; cvta.to.shared.u64 t, %1; cvt.u32.u64 %0, t; }" : "=r"(a) : "l"(p));
    return a;
}
__device__ __forceinline__ void ldsm4(uint32_t* r, uint32_t addr) {
    asm volatile("ldmatrix.sync.aligned.m8n8.x4.shared.b16 {%0,%1,%2,%3}, [%4];"
        : "=r"(r[0]), "=r"(r[1]), "=r"(r[2]), "=r"(r[3]) : "r"(addr));
}
__device__ __forceinline__ void ldsm4t(uint32_t* r, uint32_t addr) {
    asm volatile("ldmatrix.sync.aligned.m8n8.x4.trans.shared.b16 {%0,%1,%2,%3}, [%4];"
        : "=r"(r[0]), "=r"(r[1]), "=r"(r[2]), "=r"(r[3]) : "r"(addr));
}
__device__ __forceinline__ void mma16816(float* c, const uint32_t* a, const uint32_t* b) {
    asm volatile(
        "mma.sync.aligned.m16n8k16.row.col.f32.bf16.bf16.f32 "
        "{%0,%1,%2,%3}, {%4,%5,%6,%7}, {%8,%9}, {%0,%1,%2,%3};"
        : "+f"(c[0]), "+f"(c[1]), "+f"(c[2]), "+f"(c[3])
        : "r"(a[0]), "r"(a[1]), "r"(a[2]), "r"(a[3]), "r"(b[0]), "r"(b[1]));
}
__device__ __forceinline__ uint32_t packbf(float x, float y) {
    __nv_bfloat162 h = __floats2bfloat162_rn(x, y);
    return *(uint32_t*)&h;
}
__device__ __forceinline__ void split2(float x, float y, uint32_t& h, uint32_t& l) {
    __nv_bfloat16 hx = __float2bfloat16(x), hy = __float2bfloat16(y);
    h = packbf(x, y);
    l = packbf(x - __bfloat162float(hx), y - __bfloat162float(hy));
}
#define CP_ASYNC16(dst, src) \
    asm volatile("cp.async.cg.shared.global [%0], [%1], 16;" :: "r"(dst), "l"(src))
#define CP_COMMIT() asm volatile("cp.async.commit_group;")
#define CP_WAIT(n)  asm volatile("cp.async.wait_group %0;" :: "n"(n))

// ---------------- GEMM smem layout: 3 cp.async stages (best measured) -------
#define TROW 80
#define BUF_B (128*TROW)
#define STAGE_B (4*BUF_B)
#define NSTG 3
#define OFF_BIAS (NSTG*STAGE_B)
#define GEMM_SMEM (OFF_BIAS + 512)
#define NCHUNK (DD/32)

// ---------------------------------------------------------------------------
// Fused prep kernel
// ---------------------------------------------------------------------------
#define PREP_SPLIT_CTAS (MM*DD/1024)          // 6144
#define PREP_T1_CTAS    ((N3/32)*(DD/32))     // 1728
#define PREP_T2_CTAS    ((DD/32)*(DD/32))     // 576
#define PREP_CTAS (PREP_SPLIT_CTAS + PREP_T1_CTAS + PREP_T2_CTAS)

__device__ __forceinline__ void transpose_split_body(
    const float* __restrict__ src, __nv_bfloat16* __restrict__ hi,
    __nv_bfloat16* __restrict__ lo, int R, int C, int bx, int by)
{
    __shared__ float t[32][33];
    int tx = threadIdx.x & 31, ty = threadIdx.x >> 5;
#pragma unroll
    for (int i = 0; i < 32; i += 8)
        t[ty + i][tx] = src[(size_t)(by + ty + i) * C + bx + tx];
    __syncthreads();
#pragma unroll
    for (int i = 0; i < 32; i += 8) {
        float v = t[tx][ty + i];
        __nv_bfloat16 h = __float2bfloat16(v);
        size_t o = (size_t)(bx + ty + i) * R + by + tx;
        hi[o] = h; lo[o] = __float2bfloat16(v - __bfloat162float(h));
    }
}

__global__ __launch_bounds__(256) void prep_kernel(
    const float* __restrict__ x, const float* __restrict__ Wqkv,
    const float* __restrict__ Wout)
{
    int b = blockIdx.x;
    if (b < PREP_SPLIT_CTAS) {
        int i = (b * 256 + threadIdx.x) * 4;
        float4 v = *(const float4*)(x + i);
        uint32_t h0, l0, h1, l1;
        split2(v.x, v.y, h0, l0);
        split2(v.z, v.w, h1, l1);
        *(uint32_t*)(g_xh + i) = h0; *(uint32_t*)(g_xh + i + 2) = h1;
        *(uint32_t*)(g_xl + i) = l0; *(uint32_t*)(g_xl + i + 2) = l1;
    } else if (b < PREP_SPLIT_CTAS + PREP_T1_CTAS) {
        int bb = b - PREP_SPLIT_CTAS;
        int bx = (bb % (N3/32)) * 32, by = (bb / (N3/32)) * 32;
        transpose_split_body(Wqkv, g_w1h, g_w1l, DD, N3, bx, by);
    } else {
        int bb = b - PREP_SPLIT_CTAS - PREP_T1_CTAS;
        int bx = (bb % (DD/32)) * 32, by = (bb / (DD/32)) * 32;
        transpose_split_body(Wout, g_w2h, g_w2l, DD, DD, bx, by);
    }
}

// ---------------------------------------------------------------------------
// bf16x3 MMA mainloop (round-14 proven)
// ---------------------------------------------------------------------------
__device__ __forceinline__ void gemm_mainloop(
    const __nv_bfloat16* __restrict__ Ah, const __nv_bfloat16* __restrict__ Al,
    const __nv_bfloat16* __restrict__ Bh, const __nv_bfloat16* __restrict__ Bl,
    const float* __restrict__ bias_g,
    char* sm, uint32_t smb, int row0, int col0, float c[2][4][4])
{
    const int tid  = threadIdx.x;
    const int wid  = tid >> 5, lane = tid & 31;
    const int wr   = wid >> 2, wc = wid & 3;

    if (tid < 128) ((float*)(sm + OFF_BIAS))[tid] = bias_g[col0 + tid];

    const int crow = tid >> 2;
    const int ck8  = (tid & 3) * 8;
    const __nv_bfloat16* gA_h = Ah + (size_t)(row0 + crow) * DD + ck8;
    const __nv_bfloat16* gA_l = Al + (size_t)(row0 + crow) * DD + ck8;
    const __nv_bfloat16* gB_h = Bh + (size_t)(col0 + crow) * DD + ck8;
    const __nv_bfloat16* gB_l = Bl + (size_t)(col0 + crow) * DD + ck8;
    const uint32_t sdst = smb + (uint32_t)(crow * TROW + ck8 * 2);

#pragma unroll
    for (int p = 0; p < 2; p++) {
        const uint32_t so = sdst + (uint32_t)p * STAGE_B;
        const int ko = p * 32;
        CP_ASYNC16(so,             gA_h + ko);
        CP_ASYNC16(so + BUF_B,     gA_l + ko);
        CP_ASYNC16(so + 2*BUF_B,   gB_h + ko);
        CP_ASYNC16(so + 3*BUF_B,   gB_l + ko);
        CP_COMMIT();
    }

    const int lrow = lane & 15;
    const int lk   = (lane >> 4) * 8;

    int st = 0;
    for (int ch = 0; ch < NCHUNK; ch++) {
        CP_WAIT(1);
        __syncthreads();

        {
            int nx = ch + 2;
            if (nx < NCHUNK) {
                int stn = st + 2; if (stn >= NSTG) stn -= NSTG;
                const uint32_t so = sdst + (uint32_t)stn * STAGE_B;
                const int ko = nx * 32;
                CP_ASYNC16(so,           gA_h + ko);
                CP_ASYNC16(so + BUF_B,   gA_l + ko);
                CP_ASYNC16(so + 2*BUF_B, gB_h + ko);
                CP_ASYNC16(so + 3*BUF_B, gB_l + ko);
            }
            CP_COMMIT();
        }

        const uint32_t stg = smb + (uint32_t)st * STAGE_B;

        uint32_t a_hi[2][2][4], a_lo[2][2][4], b_hi[2][4][2], b_lo[2][4][2];
#pragma unroll
        for (int ks = 0; ks < 2; ks++) {
            const uint32_t kb = (uint32_t)((ks * 16 + lk) * 2);
#pragma unroll
            for (int mt = 0; mt < 2; mt++) {
                uint32_t ra = stg + (uint32_t)((wr * 32 + mt * 16 + lrow) * TROW) + kb;
                ldsm4(a_hi[ks][mt], ra);
                ldsm4(a_lo[ks][mt], ra + BUF_B);
            }
#pragma unroll
            for (int g = 0; g < 2; g++) {
                uint32_t rb = stg + (uint32_t)((wc * 32 + g * 16 + lrow) * TROW) + kb;
                uint32_t r[4];
                ldsm4(r, rb + 2*BUF_B);
                b_hi[ks][2*g][0] = r[0]; b_hi[ks][2*g][1] = r[2];
                b_hi[ks][2*g+1][0] = r[1]; b_hi[ks][2*g+1][1] = r[3];
                ldsm4(r, rb + 3*BUF_B);
                b_lo[ks][2*g][0] = r[0]; b_lo[ks][2*g][1] = r[2];
                b_lo[ks][2*g+1][0] = r[1]; b_lo[ks][2*g+1][1] = r[3];
            }
        }
#pragma unroll
        for (int ks = 0; ks < 2; ks++) {
#pragma unroll
            for (int mt = 0; mt < 2; mt++)
#pragma unroll
                for (int nt = 0; nt < 4; nt++)
                    mma16816(c[mt][nt], a_hi[ks][mt], b_hi[ks][nt]);
#pragma unroll
            for (int mt = 0; mt < 2; mt++)
#pragma unroll
                for (int nt = 0; nt < 4; nt++)
                    mma16816(c[mt][nt], a_hi[ks][mt], b_lo[ks][nt]);
#pragma unroll
            for (int mt = 0; mt < 2; mt++)
#pragma unroll
                for (int nt = 0; nt < 4; nt++)
                    mma16816(c[mt][nt], a_lo[ks][mt], b_hi[ks][nt]);
        }
        st++; if (st >= NSTG) st = 0;
    }
    __syncthreads();
}

// ---------------------------------------------------------------------------
// GEMM1: qkv projection -> bf16 hi/lo Q(scaled incl. log2e)/K/V in [b,h,s,d]
// ---------------------------------------------------------------------------
__global__ __launch_bounds__(512) void gemm_qkv_tc(const float* __restrict__ bqkv)
{
    extern __shared__ char sm[];
    const uint32_t smb = smem_u32(sm);
    const int col0 = blockIdx.x * 128;
    const int row0 = blockIdx.y * 128;
    const int tid = threadIdx.x, wid = tid >> 5, lane = tid & 31;
    const int wr = wid >> 2, wc = wid & 3;

    float c[2][4][4] = {};
    gemm_mainloop(g_xh, g_xl, g_w1h, g_w1l, bqkv, sm, smb, row0, col0, c);

    const float* bias_s = (const float*)(sm + OFF_BIAS);
    const int which = col0 / DD;
    const int h0 = (col0 % DD) / HD;
    const int b_ = row0 >> 12;
    const int s0 = row0 & 4095;
    const float scale = (which == 0) ? 0.125f * 1.44269504088896f : 1.0f;

    __nv_bfloat16* dh = (which == 0) ? g_qh : (which == 1) ? g_kh : g_vh;
    __nv_bfloat16* dl = (which == 0) ? g_ql : (which == 1) ? g_kl : g_vl;

#pragma unroll
    for (int mt = 0; mt < 2; mt++)
#pragma unroll
        for (int nt = 0; nt < 4; nt++) {
            int cl = wc * 32 + nt * 8 + (lane & 3) * 2;
            int h  = h0 + (cl >> 6);
            int d  = cl & 63;
            float bx = bias_s[cl], by = bias_s[cl + 1];
            const size_t base = (size_t)(b_ * HH + h) * SS * HD;
#pragma unroll
            for (int hh = 0; hh < 2; hh++) {
                int gs = s0 + wr * 32 + mt * 16 + (lane >> 2) + hh * 8;
                float v0 = (c[mt][nt][2*hh]   + bx) * scale;
                float v1 = (c[mt][nt][2*hh+1] + by) * scale;
                uint32_t hp, lp;
                split2(v0, v1, hp, lp);
                *(uint32_t*)&dh[base + (size_t)gs * HD + d] = hp;
                *(uint32_t*)&dl[base + (size_t)gs * HD + d] = lp;
            }
        }
}

// ---------------------------------------------------------------------------
// GEMM2: out projection
// ---------------------------------------------------------------------------
__global__ __launch_bounds__(512) void gemm_out_tc(const float* __restrict__ bout,
                                                   float* __restrict__ Y)
{
    extern __shared__ char sm[];
    const uint32_t smb = smem_u32(sm);
    const int col0 = blockIdx.x * 128;
    const int row0 = blockIdx.y * 128;
    const int tid = threadIdx.x, wid = tid >> 5, lane = tid & 31;
    const int wr = wid >> 2, wc = wid & 3;

    float c[2][4][4] = {};
    gemm_mainloop(g_oh, g_ol, g_w2h, g_w2l, bout, sm, smb, row0, col0, c);

    const float* bias_s = (const float*)(sm + OFF_BIAS);
#pragma unroll
    for (int mt = 0; mt < 2; mt++)
#pragma unroll
        for (int nt = 0; nt < 4; nt++) {
            int cl = wc * 32 + nt * 8 + (lane & 3) * 2;
            float bx = bias_s[cl], by = bias_s[cl + 1];
#pragma unroll
            for (int hh = 0; hh < 2; hh++) {
                int r = row0 + wr * 32 + mt * 16 + (lane >> 2) + hh * 8;
                float2 v = make_float2(c[mt][nt][2*hh] + bx, c[mt][nt][2*hh+1] + by);
                *(float2*)&Y[(size_t)r * DD + col0 + cl] = v;
            }
        }
}

// ---------------------------------------------------------------------------
// Flash attention: deferred 128-key softmax (exp2), 4 KV buffers (2 per pair,
// ping-pong across pairs) -> 2 syncs per round instead of 3.
// ---------------------------------------------------------------------------
#define KST 72
#define QBYTES (128*KST*2)
#define KBYTES (64*KST*2)
#define ABUF (4*KBYTES)             // 36864 per KV tile buffer
#define ATTN_SMEM (4*ABUF)          // 147456

__global__ __launch_bounds__(256) void attn_mma_kernel()
{
    extern __shared__ char smc[];
    const uint32_t smb = smem_u32(smc);
    const int qt  = gridDim.x - 1 - blockIdx.x;
    const int bh  = blockIdx.y;
    const int tid = threadIdx.x;
    const int wid = tid >> 5, lane = tid & 31;
    const int lrow = lane & 15, lk = (lane >> 4) * 8;

    const size_t bhoff = (size_t)bh * SS * HD;
    const __nv_bfloat16* Qhg = g_qh + bhoff;
    const __nv_bfloat16* Qlg = g_ql + bhoff;
    const __nv_bfloat16* Khg = g_kh + bhoff;
    const __nv_bfloat16* Klg = g_kl + bhoff;
    const __nv_bfloat16* Vhg = g_vh + bhoff;
    const __nv_bfloat16* Vlg = g_vl + bhoff;

    // ---- Q stage (uses buffer pair 0 region as staging) ----
    {
        __nv_bfloat16* qs = (__nv_bfloat16*)smc;
#pragma unroll
        for (int i = 0; i < 4; i++) {
            int f = tid + i * 256;
            int r = f >> 3, c8 = (f & 7) * 8;
            *(uint4*)&qs[r * KST + c8] =
                *(const uint4*)&Qhg[(size_t)(qt * 128 + r) * HD + c8];
            *(uint4*)&qs[128 * KST + r * KST + c8] =
                *(const uint4*)&Qlg[(size_t)(qt * 128 + r) * HD + c8];
        }
    }
    __syncthreads();

    uint32_t qh[4][4], ql[4][4];
#pragma unroll
    for (int t = 0; t < 4; t++) {
        uint32_t a = smb + (uint32_t)((wid * 16 + lrow) * KST + t * 16 + lk) * 2;
        ldsm4(qh[t], a);
        ldsm4(ql[t], a + QBYTES);
    }
    __syncthreads();   // Q frags extracted before pair-0 buffers overwritten

    float o[8][4] = {};
    float m0 = -1e30f, m1 = -1e30f, l0 = 0.f, l1 = 0.f;

    uint4 pk[2][4];
#pragma unroll
    for (int i = 0; i < 2; i++) {
        int f = tid + i * 256;
        int r = f >> 3, c8 = (f & 7) * 8;
        size_t go = (size_t)r * HD + c8;
        pk[i][0] = *(const uint4*)&Khg[go];
        pk[i][1] = *(const uint4*)&Klg[go];
        pk[i][2] = *(const uint4*)&Vhg[go];
        pk[i][3] = *(const uint4*)&Vlg[go];
    }

    for (int p = 0; p <= qt; p++) {
        float s0[8][4] = {}, s1[8][4] = {};
        const uint32_t pb = (uint32_t)((p & 1) * 2 * ABUF);   // pair base: 0 or 2*ABUF

        // ===== phase A: tile 2p -> buf pb+0 (no loop-top sync: other pair) ==
        {
            __nv_bfloat16* ks = (__nv_bfloat16*)(smc + pb);
#pragma unroll
            for (int i = 0; i < 2; i++) {
                int f = tid + i * 256;
                int r = f >> 3, c8 = (f & 7) * 8;
                int so = r * KST + c8;
                *(uint4*)&ks[so]            = pk[i][0];
                *(uint4*)&ks[64*KST   + so] = pk[i][1];
                *(uint4*)&ks[2*64*KST + so] = pk[i][2];
                *(uint4*)&ks[3*64*KST + so] = pk[i][3];
            }
        }
        __syncthreads();

#pragma unroll
        for (int i = 0; i < 2; i++) {
            int f = tid + i * 256;
            int r = f >> 3, c8 = (f & 7) * 8;
            size_t go = (size_t)((2 * p + 1) * 64 + r) * HD + c8;
            pk[i][0] = *(const uint4*)&Khg[go];
            pk[i][1] = *(const uint4*)&Klg[go];
            pk[i][2] = *(const uint4*)&Vhg[go];
            pk[i][3] = *(const uint4*)&Vlg[go];
        }

#pragma unroll
        for (int t = 0; t < 4; t++) {
#pragma unroll
            for (int g = 0; g < 4; g++) {
                uint32_t a = smb + pb + (uint32_t)((g * 16 + lrow) * KST + t * 16 + lk) * 2;
                uint32_t rh[4], rl[4];
                ldsm4(rh, a);
                ldsm4(rl, a + KBYTES);
                uint32_t bh0[2] = {rh[0], rh[2]}, bh1[2] = {rh[1], rh[3]};
                uint32_t bl0[2] = {rl[0], rl[2]}, bl1[2] = {rl[1], rl[3]};
                mma16816(s0[2*g],   qh[t], bh0);
                mma16816(s0[2*g+1], qh[t], bh1);
                mma16816(s0[2*g],   qh[t], bl0);
                mma16816(s0[2*g+1], qh[t], bl1);
                mma16816(s0[2*g],   ql[t], bh0);
                mma16816(s0[2*g+1], ql[t], bh1);
            }
        }

        // ===== phase B: tile 2p+1 -> buf pb+ABUF =====
        {
            __nv_bfloat16* ks = (__nv_bfloat16*)(smc + pb + ABUF);
#pragma unroll
            for (int i = 0; i < 2; i++) {
                int f = tid + i * 256;
                int r = f >> 3, c8 = (f & 7) * 8;
                int so = r * KST + c8;
                *(uint4*)&ks[so]            = pk[i][0];
                *(uint4*)&ks[64*KST   + so] = pk[i][1];
                *(uint4*)&ks[2*64*KST + so] = pk[i][2];
                *(uint4*)&ks[3*64*KST + so] = pk[i][3];
            }
        }
        __syncthreads();

        if (p < qt) {
#pragma unroll
            for (int i = 0; i < 2; i++) {
                int f = tid + i * 256;
                int r = f >> 3, c8 = (f & 7) * 8;
                size_t go = (size_t)((2 * p + 2) * 64 + r) * HD + c8;
                pk[i][0] = *(const uint4*)&Khg[go];
                pk[i][1] = *(const uint4*)&Klg[go];
                pk[i][2] = *(const uint4*)&Vhg[go];
                pk[i][3] = *(const uint4*)&Vlg[go];
            }
        }

#pragma unroll
        for (int t = 0; t < 4; t++) {
#pragma unroll
            for (int g = 0; g < 4; g++) {
                uint32_t a = smb + pb + (uint32_t)ABUF +
                             (uint32_t)((g * 16 + lrow) * KST + t * 16 + lk) * 2;
                uint32_t rh[4], rl[4];
                ldsm4(rh, a);
                ldsm4(rl, a + KBYTES);
                uint32_t bh0[2] = {rh[0], rh[2]}, bh1[2] = {rh[1], rh[3]};
                uint32_t bl0[2] = {rl[0], rl[2]}, bl1[2] = {rl[1], rl[3]};
                mma16816(s1[2*g],   qh[t], bh0);
                mma16816(s1[2*g+1], qh[t], bh1);
                mma16816(s1[2*g],   qh[t], bl0);
                mma16816(s1[2*g+1], qh[t], bl1);
                mma16816(s1[2*g],   ql[t], bh0);
                mma16816(s1[2*g+1], ql[t], bh1);
            }
        }

        // ===== causal mask (diagonal pair only) =====
        if (p == qt) {
            int rbase = qt * 128 + wid * 16 + (lane >> 2);
            int cb0 = 2 * p * 64 + (lane & 3) * 2;
#pragma unroll
            for (int n = 0; n < 8; n++) {
                int cc = cb0 + n * 8;
                if (cc      > rbase)     s0[n][0] = -1e30f;
                if (cc + 1  > rbase)     s0[n][1] = -1e30f;
                if (cc      > rbase + 8) s0[n][2] = -1e30f;
                if (cc + 1  > rbase + 8) s0[n][3] = -1e30f;
                int cd = cc + 64;
                if (cd      > rbase)     s1[n][0] = -1e30f;
                if (cd + 1  > rbase)     s1[n][1] = -1e30f;
                if (cd      > rbase + 8) s1[n][2] = -1e30f;
                if (cd + 1  > rbase + 8) s1[n][3] = -1e30f;
            }
        }

        // ===== single online-softmax round over 128 keys (base-2) =====
        float mx0 = -1e30f, mx1 = -1e30f;
#pragma unroll
        for (int n = 0; n < 8; n++) {
            mx0 = fmaxf(mx0, fmaxf(fmaxf(s0[n][0], s0[n][1]), fmaxf(s1[n][0], s1[n][1])));
            mx1 = fmaxf(mx1, fmaxf(fmaxf(s0[n][2], s0[n][3]), fmaxf(s1[n][2], s1[n][3])));
        }
        mx0 = fmaxf(mx0, __shfl_xor_sync(0xffffffffu, mx0, 1));
        mx0 = fmaxf(mx0, __shfl_xor_sync(0xffffffffu, mx0, 2));
        mx1 = fmaxf(mx1, __shfl_xor_sync(0xffffffffu, mx1, 1));
        mx1 = fmaxf(mx1, __shfl_xor_sync(0xffffffffu, mx1, 2));
        float mn0 = fmaxf(m0, mx0), mn1 = fmaxf(m1, mx1);
        float a0 = exp2f(m0 - mn0), a1 = exp2f(m1 - mn1);
        m0 = mn0; m1 = mn1;
        float lt0 = 0.f, lt1 = 0.f;
#pragma unroll
        for (int n = 0; n < 8; n++) {
            s0[n][0] = exp2f(s0[n][0] - mn0); lt0 += s0[n][0];
            s0[n][1] = exp2f(s0[n][1] - mn0); lt0 += s0[n][1];
            s0[n][2] = exp2f(s0[n][2] - mn1); lt1 += s0[n][2];
            s0[n][3] = exp2f(s0[n][3] - mn1); lt1 += s0[n][3];
            s1[n][0] = exp2f(s1[n][0] - mn0); lt0 += s1[n][0];
            s1[n][1] = exp2f(s1[n][1] - mn0); lt0 += s1[n][1];
            s1[n][2] = exp2f(s1[n][2] - mn1); lt1 += s1[n][2];
            s1[n][3] = exp2f(s1[n][3] - mn1); lt1 += s1[n][3];
        }
        lt0 += __shfl_xor_sync(0xffffffffu, lt0, 1);
        lt0 += __shfl_xor_sync(0xffffffffu, lt0, 2);
        lt1 += __shfl_xor_sync(0xffffffffu, lt1, 1);
        lt1 += __shfl_xor_sync(0xffffffffu, lt1, 2);
        l0 = l0 * a0 + lt0;
        l1 = l1 * a1 + lt1;
#pragma unroll
        for (int n = 0; n < 8; n++) {
            o[n][0] *= a0; o[n][1] *= a0; o[n][2] *= a1; o[n][3] *= a1;
        }

        // ===== O += P0 V0 + P1 V1 =====
#pragma unroll
        for (int half = 0; half < 2; half++) {
            float (*sp)[4] = half ? s1 : s0;
            const uint32_t vbase = smb + pb + (uint32_t)(half * ABUF) + (uint32_t)(2*KBYTES);
#pragma unroll
            for (int t = 0; t < 4; t++) {
                uint32_t ph[4], pl[4];
                split2(sp[2*t][0],   sp[2*t][1],   ph[0], pl[0]);
                split2(sp[2*t][2],   sp[2*t][3],   ph[1], pl[1]);
                split2(sp[2*t+1][0], sp[2*t+1][1], ph[2], pl[2]);
                split2(sp[2*t+1][2], sp[2*t+1][3], ph[3], pl[3]);
#pragma unroll
                for (int g = 0; g < 4; g++) {
                    uint32_t a = vbase +
                                 (uint32_t)((t * 16 + lrow) * KST + g * 16 + lk) * 2;
                    uint32_t rh[4], rl[4];
                    ldsm4t(rh, a);
                    ldsm4t(rl, a + KBYTES);
                    uint32_t bh0[2] = {rh[0], rh[1]}, bh1[2] = {rh[2], rh[3]};
                    uint32_t bl0[2] = {rl[0], rl[1]}, bl1[2] = {rl[2], rl[3]};
                    mma16816(o[2*g],   ph, bh0);
                    mma16816(o[2*g+1], ph, bh1);
                    mma16816(o[2*g],   ph, bl0);
                    mma16816(o[2*g+1], ph, bl1);
                    mma16816(o[2*g],   pl, bh0);
                    mma16816(o[2*g+1], pl, bh1);
                }
            }
        }
    }

    // ---- epilogue ----
    float inv0 = 1.f / l0, inv1 = 1.f / l1;
    const int b_ = bh / HH, h_ = bh % HH;
    const size_t r0 = (size_t)(b_ * SS + qt * 128 + wid * 16 + (lane >> 2));
#pragma unroll
    for (int n = 0; n < 8; n++) {
        int d = h_ * 64 + n * 8 + (lane & 3) * 2;
        uint32_t hp, lp;
        split2(o[n][0] * inv0, o[n][1] * inv0, hp, lp);
        *(uint32_t*)&g_oh[r0 * DD + d] = hp;
        *(uint32_t*)&g_ol[r0 * DD + d] = lp;
        split2(o[n][2] * inv1, o[n][3] * inv1, hp, lp);
        *(uint32_t*)&g_oh[(r0 + 8) * DD + d] = hp;
        *(uint32_t*)&g_ol[(r0 + 8) * DD + d] = lp;
    }
}

// ---------------------------------------------------------------------------
extern "C" void kernel_launch(void* const* d_in, const int* in_sizes, int n_in,
                              void* d_out, int out_size)
{
    const float* x    = (const float*)d_in[0];
    const float* Wqkv = (const float*)d_in[1];
    const float* bqkv = (const float*)d_in[2];
    const float* Wout = (const float*)d_in[3];
    const float* bout = (const float*)d_in[4];
    float* out = (float*)d_out;

    cudaFuncSetAttribute(attn_mma_kernel, cudaFuncAttributeMaxDynamicSharedMemorySize, ATTN_SMEM);
    cudaFuncSetAttribute(gemm_qkv_tc, cudaFuncAttributeMaxDynamicSharedMemorySize, GEMM_SMEM);
    cudaFuncSetAttribute(gemm_out_tc, cudaFuncAttributeMaxDynamicSharedMemorySize, GEMM_SMEM);

    prep_kernel<<<PREP_CTAS, 256>>>(x, Wqkv, Wout);
    gemm_qkv_tc<<<dim3(N3 / 128, MM / 128), 512, GEMM_SMEM>>>(bqkv);
    attn_mma_kernel<<<dim3(SS / 128, BB * HH), 256, ATTN_SMEM>>>();
    gemm_out_tc<<<dim3(DD / 128, MM / 128), 512, GEMM_SMEM>>>(bout, out);
}

// round 16
// speedup vs baseline: 1.0529x; 1.0529x over previous
#include <cuda_runtime.h>
#include <cuda_bf16.h>
#include <cstdint>

#define BB 2
#define SS 4096
#define DD 768
#define HH 12
#define HD 64
#define N3 (3*DD)
#define MM (BB*SS)

// bf16 hi/lo scratch
__device__ __align__(16) __nv_bfloat16 g_qh[BB*HH*SS*HD], g_ql[BB*HH*SS*HD];
__device__ __align__(16) __nv_bfloat16 g_kh[BB*HH*SS*HD], g_kl[BB*HH*SS*HD];
__device__ __align__(16) __nv_bfloat16 g_vh[BB*HH*SS*HD], g_vl[BB*HH*SS*HD];
__device__ __align__(16) __nv_bfloat16 g_oh[MM*DD],  g_ol[MM*DD];
__device__ __align__(16) __nv_bfloat16 g_xh[MM*DD],  g_xl[MM*DD];
__device__ __align__(16) __nv_bfloat16 g_w1h[N3*DD], g_w1l[N3*DD];
__device__ __align__(16) __nv_bfloat16 g_w2h[DD*DD], g_w2l[DD*DD];

// ---------------- helpers ----------------
__device__ __forceinline__ uint32_t smem_u32(const void* p) {
    uint32_t a;
    asm("{ .reg .u64 t; cvta.to.shared.u64 t, %1; cvt.u32.u64 %0, t; }" : "=r"(a) : "l"(p));
    return a;
}
__device__ __forceinline__ void ldsm4(uint32_t* r, uint32_t addr) {
    asm volatile("ldmatrix.sync.aligned.m8n8.x4.shared.b16 {%0,%1,%2,%3}, [%4];"
        : "=r"(r[0]), "=r"(r[1]), "=r"(r[2]), "=r"(r[3]) : "r"(addr));
}
__device__ __forceinline__ void ldsm4t(uint32_t* r, uint32_t addr) {
    asm volatile("ldmatrix.sync.aligned.m8n8.x4.trans.shared.b16 {%0,%1,%2,%3}, [%4];"
        : "=r"(r[0]), "=r"(r[1]), "=r"(r[2]), "=r"(r[3]) : "r"(addr));
}
__device__ __forceinline__ void mma16816(float* c, const uint32_t* a, const uint32_t* b) {
    asm volatile(
        "mma.sync.aligned.m16n8k16.row.col.f32.bf16.bf16.f32 "
        "{%0,%1,%2,%3}, {%4,%5,%6,%7}, {%8,%9}, {%0,%1,%2,%3};"
        : "+f"(c[0]), "+f"(c[1]), "+f"(c[2]), "+f"(c[3])
        : "r"(a[0]), "r"(a[1]), "r"(a[2]), "r"(a[3]), "r"(b[0]), "r"(b[1]));
}
__device__ __forceinline__ uint32_t packbf(float x, float y) {
    __nv_bfloat162 h = __floats2bfloat162_rn(x, y);
    return *(uint32_t*)&h;
}
__device__ __forceinline__ void split2(float x, float y, uint32_t& h, uint32_t& l) {
    __nv_bfloat16 hx = __float2bfloat16(x), hy = __float2bfloat16(y);
    h = packbf(x, y);
    l = packbf(x - __bfloat162float(hx), y - __bfloat162float(hy));
}
#define CP_ASYNC16(dst, src) \
    asm volatile("cp.async.ca.shared.global [%0], [%1], 16;" :: "r"(dst), "l"(src))
#define CP_COMMIT() asm volatile("cp.async.commit_group;")
#define CP_WAIT(n)  asm volatile("cp.async.wait_group %0;" :: "n"(n))

// ---------------- GEMM smem layout: 3 cp.async stages (best measured) -------
#define TROW 80
#define BUF_B (128*TROW)
#define STAGE_B (4*BUF_B)
#define NSTG 3
#define OFF_BIAS (NSTG*STAGE_B)
#define GEMM_SMEM (OFF_BIAS + 512)
#define NCHUNK (DD/32)

// ---------------------------------------------------------------------------
// Fused prep kernel
// ---------------------------------------------------------------------------
#define PREP_SPLIT_CTAS (MM*DD/1024)          // 6144
#define PREP_T1_CTAS    ((N3/32)*(DD/32))     // 1728
#define PREP_T2_CTAS    ((DD/32)*(DD/32))     // 576
#define PREP_CTAS (PREP_SPLIT_CTAS + PREP_T1_CTAS + PREP_T2_CTAS)

__device__ __forceinline__ void transpose_split_body(
    const float* __restrict__ src, __nv_bfloat16* __restrict__ hi,
    __nv_bfloat16* __restrict__ lo, int R, int C, int bx, int by)
{
    __shared__ float t[32][33];
    int tx = threadIdx.x & 31, ty = threadIdx.x >> 5;
#pragma unroll
    for (int i = 0; i < 32; i += 8)
        t[ty + i][tx] = src[(size_t)(by + ty + i) * C + bx + tx];
    __syncthreads();
#pragma unroll
    for (int i = 0; i < 32; i += 8) {
        float v = t[tx][ty + i];
        __nv_bfloat16 h = __float2bfloat16(v);
        size_t o = (size_t)(bx + ty + i) * R + by + tx;
        hi[o] = h; lo[o] = __float2bfloat16(v - __bfloat162float(h));
    }
}

__global__ __launch_bounds__(256) void prep_kernel(
    const float* __restrict__ x, const float* __restrict__ Wqkv,
    const float* __restrict__ Wout)
{
    int b = blockIdx.x;
    if (b < PREP_SPLIT_CTAS) {
        int i = (b * 256 + threadIdx.x) * 4;
        float4 v = *(const float4*)(x + i);
        uint32_t h0, l0, h1, l1;
        split2(v.x, v.y, h0, l0);
        split2(v.z, v.w, h1, l1);
        *(uint32_t*)(g_xh + i) = h0; *(uint32_t*)(g_xh + i + 2) = h1;
        *(uint32_t*)(g_xl + i) = l0; *(uint32_t*)(g_xl + i + 2) = l1;
    } else if (b < PREP_SPLIT_CTAS + PREP_T1_CTAS) {
        int bb = b - PREP_SPLIT_CTAS;
        int bx = (bb % (N3/32)) * 32, by = (bb / (N3/32)) * 32;
        transpose_split_body(Wqkv, g_w1h, g_w1l, DD, N3, bx, by);
    } else {
        int bb = b - PREP_SPLIT_CTAS - PREP_T1_CTAS;
        int bx = (bb % (DD/32)) * 32, by = (bb / (DD/32)) * 32;
        transpose_split_body(Wout, g_w2h, g_w2l, DD, DD, bx, by);
    }
}

// ---------------------------------------------------------------------------
// bf16x3 MMA mainloop: 3-stage cp.async (.ca), issue-before-wait pacing,
// both k-steps' fragments preloaded, term-major mma ordering.
// ---------------------------------------------------------------------------
__device__ __forceinline__ void gemm_mainloop(
    const __nv_bfloat16* __restrict__ Ah, const __nv_bfloat16* __restrict__ Al,
    const __nv_bfloat16* __restrict__ Bh, const __nv_bfloat16* __restrict__ Bl,
    const float* __restrict__ bias_g,
    char* sm, uint32_t smb, int row0, int col0, float c[2][4][4])
{
    const int tid  = threadIdx.x;
    const int wid  = tid >> 5, lane = tid & 31;
    const int wr   = wid >> 2, wc = wid & 3;

    if (tid < 128) ((float*)(sm + OFF_BIAS))[tid] = bias_g[col0 + tid];

    const int crow = tid >> 2;
    const int ck8  = (tid & 3) * 8;
    const __nv_bfloat16* gA_h = Ah + (size_t)(row0 + crow) * DD + ck8;
    const __nv_bfloat16* gA_l = Al + (size_t)(row0 + crow) * DD + ck8;
    const __nv_bfloat16* gB_h = Bh + (size_t)(col0 + crow) * DD + ck8;
    const __nv_bfloat16* gB_l = Bl + (size_t)(col0 + crow) * DD + ck8;
    const uint32_t sdst = smb + (uint32_t)(crow * TROW + ck8 * 2);

#pragma unroll
    for (int p = 0; p < 2; p++) {
        const uint32_t so = sdst + (uint32_t)p * STAGE_B;
        const int ko = p * 32;
        CP_ASYNC16(so,             gA_h + ko);
        CP_ASYNC16(so + BUF_B,     gA_l + ko);
        CP_ASYNC16(so + 2*BUF_B,   gB_h + ko);
        CP_ASYNC16(so + 3*BUF_B,   gB_l + ko);
        CP_COMMIT();
    }

    const int lrow = lane & 15;
    const int lk   = (lane >> 4) * 8;

    int st = 0;
    for (int ch = 0; ch < NCHUNK; ch++) {
        // issue chunk ch+2 FIRST (stage st+2 is free: consumed at ch-1),
        // then wait leaving 2 groups in flight -> stage st (chunk ch) ready.
        {
            int nx = ch + 2;
            if (nx < NCHUNK) {
                int stn = st + 2; if (stn >= NSTG) stn -= NSTG;
                const uint32_t so = sdst + (uint32_t)stn * STAGE_B;
                const int ko = nx * 32;
                CP_ASYNC16(so,           gA_h + ko);
                CP_ASYNC16(so + BUF_B,   gA_l + ko);
                CP_ASYNC16(so + 2*BUF_B, gB_h + ko);
                CP_ASYNC16(so + 3*BUF_B, gB_l + ko);
            }
            CP_COMMIT();
        }
        CP_WAIT(2);
        __syncthreads();

        const uint32_t stg = smb + (uint32_t)st * STAGE_B;

        uint32_t a_hi[2][2][4], a_lo[2][2][4], b_hi[2][4][2], b_lo[2][4][2];
#pragma unroll
        for (int ks = 0; ks < 2; ks++) {
            const uint32_t kb = (uint32_t)((ks * 16 + lk) * 2);
#pragma unroll
            for (int mt = 0; mt < 2; mt++) {
                uint32_t ra = stg + (uint32_t)((wr * 32 + mt * 16 + lrow) * TROW) + kb;
                ldsm4(a_hi[ks][mt], ra);
                ldsm4(a_lo[ks][mt], ra + BUF_B);
            }
#pragma unroll
            for (int g = 0; g < 2; g++) {
                uint32_t rb = stg + (uint32_t)((wc * 32 + g * 16 + lrow) * TROW) + kb;
                uint32_t r[4];
                ldsm4(r, rb + 2*BUF_B);
                b_hi[ks][2*g][0] = r[0]; b_hi[ks][2*g][1] = r[2];
                b_hi[ks][2*g+1][0] = r[1]; b_hi[ks][2*g+1][1] = r[3];
                ldsm4(r, rb + 3*BUF_B);
                b_lo[ks][2*g][0] = r[0]; b_lo[ks][2*g][1] = r[2];
                b_lo[ks][2*g+1][0] = r[1]; b_lo[ks][2*g+1][1] = r[3];
            }
        }
#pragma unroll
        for (int ks = 0; ks < 2; ks++) {
#pragma unroll
            for (int mt = 0; mt < 2; mt++)
#pragma unroll
                for (int nt = 0; nt < 4; nt++)
                    mma16816(c[mt][nt], a_hi[ks][mt], b_hi[ks][nt]);
#pragma unroll
            for (int mt = 0; mt < 2; mt++)
#pragma unroll
                for (int nt = 0; nt < 4; nt++)
                    mma16816(c[mt][nt], a_hi[ks][mt], b_lo[ks][nt]);
#pragma unroll
            for (int mt = 0; mt < 2; mt++)
#pragma unroll
                for (int nt = 0; nt < 4; nt++)
                    mma16816(c[mt][nt], a_lo[ks][mt], b_hi[ks][nt]);
        }
        st++; if (st >= NSTG) st = 0;
    }
    __syncthreads();
}

// ---------------------------------------------------------------------------
// GEMM1: qkv projection -> bf16 hi/lo Q(scaled incl. log2e)/K/V in [b,h,s,d]
// ---------------------------------------------------------------------------
__global__ __launch_bounds__(512) void gemm_qkv_tc(const float* __restrict__ bqkv)
{
    extern __shared__ char sm[];
    const uint32_t smb = smem_u32(sm);
    const int col0 = blockIdx.x * 128;
    const int row0 = blockIdx.y * 128;
    const int tid = threadIdx.x, wid = tid >> 5, lane = tid & 31;
    const int wr = wid >> 2, wc = wid & 3;

    float c[2][4][4] = {};
    gemm_mainloop(g_xh, g_xl, g_w1h, g_w1l, bqkv, sm, smb, row0, col0, c);

    const float* bias_s = (const float*)(sm + OFF_BIAS);
    const int which = col0 / DD;
    const int h0 = (col0 % DD) / HD;
    const int b_ = row0 >> 12;
    const int s0 = row0 & 4095;
    const float scale = (which == 0) ? 0.125f * 1.44269504088896f : 1.0f;

    __nv_bfloat16* dh = (which == 0) ? g_qh : (which == 1) ? g_kh : g_vh;
    __nv_bfloat16* dl = (which == 0) ? g_ql : (which == 1) ? g_kl : g_vl;

#pragma unroll
    for (int mt = 0; mt < 2; mt++)
#pragma unroll
        for (int nt = 0; nt < 4; nt++) {
            int cl = wc * 32 + nt * 8 + (lane & 3) * 2;
            int h  = h0 + (cl >> 6);
            int d  = cl & 63;
            float bx = bias_s[cl], by = bias_s[cl + 1];
            const size_t base = (size_t)(b_ * HH + h) * SS * HD;
#pragma unroll
            for (int hh = 0; hh < 2; hh++) {
                int gs = s0 + wr * 32 + mt * 16 + (lane >> 2) + hh * 8;
                float v0 = (c[mt][nt][2*hh]   + bx) * scale;
                float v1 = (c[mt][nt][2*hh+1] + by) * scale;
                uint32_t hp, lp;
                split2(v0, v1, hp, lp);
                *(uint32_t*)&dh[base + (size_t)gs * HD + d] = hp;
                *(uint32_t*)&dl[base + (size_t)gs * HD + d] = lp;
            }
        }
}

// ---------------------------------------------------------------------------
// GEMM2: out projection
// ---------------------------------------------------------------------------
__global__ __launch_bounds__(512) void gemm_out_tc(const float* __restrict__ bout,
                                                   float* __restrict__ Y)
{
    extern __shared__ char sm[];
    const uint32_t smb = smem_u32(sm);
    const int col0 = blockIdx.x * 128;
    const int row0 = blockIdx.y * 128;
    const int tid = threadIdx.x, wid = tid >> 5, lane = tid & 31;
    const int wr = wid >> 2, wc = wid & 3;

    float c[2][4][4] = {};
    gemm_mainloop(g_oh, g_ol, g_w2h, g_w2l, bout, sm, smb, row0, col0, c);

    const float* bias_s = (const float*)(sm + OFF_BIAS);
#pragma unroll
    for (int mt = 0; mt < 2; mt++)
#pragma unroll
        for (int nt = 0; nt < 4; nt++) {
            int cl = wc * 32 + nt * 8 + (lane & 3) * 2;
            float bx = bias_s[cl], by = bias_s[cl + 1];
#pragma unroll
            for (int hh = 0; hh < 2; hh++) {
                int r = row0 + wr * 32 + mt * 16 + (lane >> 2) + hh * 8;
                float2 v = make_float2(c[mt][nt][2*hh] + bx, c[mt][nt][2*hh+1] + by);
                *(float2*)&Y[(size_t)r * DD + col0 + cl] = v;
            }
        }
}

// ---------------------------------------------------------------------------
// Flash attention (round-14 proven): deferred 128-key softmax, exp2,
// 2 KV buffers, register prefetch.
// ---------------------------------------------------------------------------
#define KST 72
#define QBYTES (128*KST*2)
#define KBYTES (64*KST*2)
#define ABUF (4*KBYTES)
#define ATTN_SMEM (2*ABUF)

__global__ __launch_bounds__(256) void attn_mma_kernel()
{
    extern __shared__ char smc[];
    const uint32_t smb = smem_u32(smc);
    const int qt  = gridDim.x - 1 - blockIdx.x;
    const int bh  = blockIdx.y;
    const int tid = threadIdx.x;
    const int wid = tid >> 5, lane = tid & 31;
    const int lrow = lane & 15, lk = (lane >> 4) * 8;

    const size_t bhoff = (size_t)bh * SS * HD;
    const __nv_bfloat16* Qhg = g_qh + bhoff;
    const __nv_bfloat16* Qlg = g_ql + bhoff;
    const __nv_bfloat16* Khg = g_kh + bhoff;
    const __nv_bfloat16* Klg = g_kl + bhoff;
    const __nv_bfloat16* Vhg = g_vh + bhoff;
    const __nv_bfloat16* Vlg = g_vl + bhoff;

    // ---- Q stage ----
    {
        __nv_bfloat16* qs = (__nv_bfloat16*)smc;
#pragma unroll
        for (int i = 0; i < 4; i++) {
            int f = tid + i * 256;
            int r = f >> 3, c8 = (f & 7) * 8;
            *(uint4*)&qs[r * KST + c8] =
                *(const uint4*)&Qhg[(size_t)(qt * 128 + r) * HD + c8];
            *(uint4*)&qs[128 * KST + r * KST + c8] =
                *(const uint4*)&Qlg[(size_t)(qt * 128 + r) * HD + c8];
        }
    }
    __syncthreads();

    uint32_t qh[4][4], ql[4][4];
#pragma unroll
    for (int t = 0; t < 4; t++) {
        uint32_t a = smb + (uint32_t)((wid * 16 + lrow) * KST + t * 16 + lk) * 2;
        ldsm4(qh[t], a);
        ldsm4(ql[t], a + QBYTES);
    }

    float o[8][4] = {};
    float m0 = -1e30f, m1 = -1e30f, l0 = 0.f, l1 = 0.f;

    uint4 pk[2][4];
#pragma unroll
    for (int i = 0; i < 2; i++) {
        int f = tid + i * 256;
        int r = f >> 3, c8 = (f & 7) * 8;
        size_t go = (size_t)r * HD + c8;
        pk[i][0] = *(const uint4*)&Khg[go];
        pk[i][1] = *(const uint4*)&Klg[go];
        pk[i][2] = *(const uint4*)&Vhg[go];
        pk[i][3] = *(const uint4*)&Vlg[go];
    }

    for (int p = 0; p <= qt; p++) {
        float s0[8][4] = {}, s1[8][4] = {};

        // ===== phase A: tile 2p -> buf0 =====
        __syncthreads();
        {
            __nv_bfloat16* ks = (__nv_bfloat16*)smc;
#pragma unroll
            for (int i = 0; i < 2; i++) {
                int f = tid + i * 256;
                int r = f >> 3, c8 = (f & 7) * 8;
                int so = r * KST + c8;
                *(uint4*)&ks[so]            = pk[i][0];
                *(uint4*)&ks[64*KST   + so] = pk[i][1];
                *(uint4*)&ks[2*64*KST + so] = pk[i][2];
                *(uint4*)&ks[3*64*KST + so] = pk[i][3];
            }
        }
        __syncthreads();

#pragma unroll
        for (int i = 0; i < 2; i++) {
            int f = tid + i * 256;
            int r = f >> 3, c8 = (f & 7) * 8;
            size_t go = (size_t)((2 * p + 1) * 64 + r) * HD + c8;
            pk[i][0] = *(const uint4*)&Khg[go];
            pk[i][1] = *(const uint4*)&Klg[go];
            pk[i][2] = *(const uint4*)&Vhg[go];
            pk[i][3] = *(const uint4*)&Vlg[go];
        }

#pragma unroll
        for (int t = 0; t < 4; t++) {
#pragma unroll
            for (int g = 0; g < 4; g++) {
                uint32_t a = smb + (uint32_t)((g * 16 + lrow) * KST + t * 16 + lk) * 2;
                uint32_t rh[4], rl[4];
                ldsm4(rh, a);
                ldsm4(rl, a + KBYTES);
                uint32_t bh0[2] = {rh[0], rh[2]}, bh1[2] = {rh[1], rh[3]};
                uint32_t bl0[2] = {rl[0], rl[2]}, bl1[2] = {rl[1], rl[3]};
                mma16816(s0[2*g],   qh[t], bh0);
                mma16816(s0[2*g+1], qh[t], bh1);
                mma16816(s0[2*g],   qh[t], bl0);
                mma16816(s0[2*g+1], qh[t], bl1);
                mma16816(s0[2*g],   ql[t], bh0);
                mma16816(s0[2*g+1], ql[t], bh1);
            }
        }

        // ===== phase B: tile 2p+1 -> buf1 =====
        {
            __nv_bfloat16* ks = (__nv_bfloat16*)(smc + ABUF);
#pragma unroll
            for (int i = 0; i < 2; i++) {
                int f = tid + i * 256;
                int r = f >> 3, c8 = (f & 7) * 8;
                int so = r * KST + c8;
                *(uint4*)&ks[so]            = pk[i][0];
                *(uint4*)&ks[64*KST   + so] = pk[i][1];
                *(uint4*)&ks[2*64*KST + so] = pk[i][2];
                *(uint4*)&ks[3*64*KST + so] = pk[i][3];
            }
        }
        __syncthreads();

        if (p < qt) {
#pragma unroll
            for (int i = 0; i < 2; i++) {
                int f = tid + i * 256;
                int r = f >> 3, c8 = (f & 7) * 8;
                size_t go = (size_t)((2 * p + 2) * 64 + r) * HD + c8;
                pk[i][0] = *(const uint4*)&Khg[go];
                pk[i][1] = *(const uint4*)&Klg[go];
                pk[i][2] = *(const uint4*)&Vhg[go];
                pk[i][3] = *(const uint4*)&Vlg[go];
            }
        }

#pragma unroll
        for (int t = 0; t < 4; t++) {
#pragma unroll
            for (int g = 0; g < 4; g++) {
                uint32_t a = smb + (uint32_t)ABUF +
                             (uint32_t)((g * 16 + lrow) * KST + t * 16 + lk) * 2;
                uint32_t rh[4], rl[4];
                ldsm4(rh, a);
                ldsm4(rl, a + KBYTES);
                uint32_t bh0[2] = {rh[0], rh[2]}, bh1[2] = {rh[1], rh[3]};
                uint32_t bl0[2] = {rl[0], rl[2]}, bl1[2] = {rl[1], rl[3]};
                mma16816(s1[2*g],   qh[t], bh0);
                mma16816(s1[2*g+1], qh[t], bh1);
                mma16816(s1[2*g],   qh[t], bl0);
                mma16816(s1[2*g+1], qh[t], bl1);
                mma16816(s1[2*g],   ql[t], bh0);
                mma16816(s1[2*g+1], ql[t], bh1);
            }
        }

        // ===== causal mask (diagonal pair only) =====
        if (p == qt) {
            int rbase = qt * 128 + wid * 16 + (lane >> 2);
            int cb0 = 2 * p * 64 + (lane & 3) * 2;
#pragma unroll
            for (int n = 0; n < 8; n++) {
                int cc = cb0 + n * 8;
                if (cc      > rbase)     s0[n][0] = -1e30f;
                if (cc + 1  > rbase)     s0[n][1] = -1e30f;
                if (cc      > rbase + 8) s0[n][2] = -1e30f;
                if (cc + 1  > rbase + 8) s0[n][3] = -1e30f;
                int cd = cc + 64;
                if (cd      > rbase)     s1[n][0] = -1e30f;
                if (cd + 1  > rbase)     s1[n][1] = -1e30f;
                if (cd      > rbase + 8) s1[n][2] = -1e30f;
                if (cd + 1  > rbase + 8) s1[n][3] = -1e30f;
            }
        }

        // ===== single online-softmax round over 128 keys (base-2) =====
        float mx0 = -1e30f, mx1 = -1e30f;
#pragma unroll
        for (int n = 0; n < 8; n++) {
            mx0 = fmaxf(mx0, fmaxf(fmaxf(s0[n][0], s0[n][1]), fmaxf(s1[n][0], s1[n][1])));
            mx1 = fmaxf(mx1, fmaxf(fmaxf(s0[n][2], s0[n][3]), fmaxf(s1[n][2], s1[n][3])));
        }
        mx0 = fmaxf(mx0, __shfl_xor_sync(0xffffffffu, mx0, 1));
        mx0 = fmaxf(mx0, __shfl_xor_sync(0xffffffffu, mx0, 2));
        mx1 = fmaxf(mx1, __shfl_xor_sync(0xffffffffu, mx1, 1));
        mx1 = fmaxf(mx1, __shfl_xor_sync(0xffffffffu, mx1, 2));
        float mn0 = fmaxf(m0, mx0), mn1 = fmaxf(m1, mx1);
        float a0 = exp2f(m0 - mn0), a1 = exp2f(m1 - mn1);
        m0 = mn0; m1 = mn1;
        float lt0 = 0.f, lt1 = 0.f;
#pragma unroll
        for (int n = 0; n < 8; n++) {
            s0[n][0] = exp2f(s0[n][0] - mn0); lt0 += s0[n][0];
            s0[n][1] = exp2f(s0[n][1] - mn0); lt0 += s0[n][1];
            s0[n][2] = exp2f(s0[n][2] - mn1); lt1 += s0[n][2];
            s0[n][3] = exp2f(s0[n][3] - mn1); lt1 += s0[n][3];
            s1[n][0] = exp2f(s1[n][0] - mn0); lt0 += s1[n][0];
            s1[n][1] = exp2f(s1[n][1] - mn0); lt0 += s1[n][1];
            s1[n][2] = exp2f(s1[n][2] - mn1); lt1 += s1[n][2];
            s1[n][3] = exp2f(s1[n][3] - mn1); lt1 += s1[n][3];
        }
        lt0 += __shfl_xor_sync(0xffffffffu, lt0, 1);
        lt0 += __shfl_xor_sync(0xffffffffu, lt0, 2);
        lt1 += __shfl_xor_sync(0xffffffffu, lt1, 1);
        lt1 += __shfl_xor_sync(0xffffffffu, lt1, 2);
        l0 = l0 * a0 + lt0;
        l1 = l1 * a1 + lt1;
#pragma unroll
        for (int n = 0; n < 8; n++) {
            o[n][0] *= a0; o[n][1] *= a0; o[n][2] *= a1; o[n][3] *= a1;
        }

        // ===== O += P0 V0 + P1 V1 =====
#pragma unroll
        for (int half = 0; half < 2; half++) {
            float (*sp)[4] = half ? s1 : s0;
            const uint32_t vbase = smb + (uint32_t)(half * ABUF) + (uint32_t)(2*KBYTES);
#pragma unroll
            for (int t = 0; t < 4; t++) {
                uint32_t ph[4], pl[4];
                split2(sp[2*t][0],   sp[2*t][1],   ph[0], pl[0]);
                split2(sp[2*t][2],   sp[2*t][3],   ph[1], pl[1]);
                split2(sp[2*t+1][0], sp[2*t+1][1], ph[2], pl[2]);
                split2(sp[2*t+1][2], sp[2*t+1][3], ph[3], pl[3]);
#pragma unroll
                for (int g = 0; g < 4; g++) {
                    uint32_t a = vbase +
                                 (uint32_t)((t * 16 + lrow) * KST + g * 16 + lk) * 2;
                    uint32_t rh[4], rl[4];
                    ldsm4t(rh, a);
                    ldsm4t(rl, a + KBYTES);
                    uint32_t bh0[2] = {rh[0], rh[1]}, bh1[2] = {rh[2], rh[3]};
                    uint32_t bl0[2] = {rl[0], rl[1]}, bl1[2] = {rl[2], rl[3]};
                    mma16816(o[2*g],   ph, bh0);
                    mma16816(o[2*g+1], ph, bh1);
                    mma16816(o[2*g],   ph, bl0);
                    mma16816(o[2*g+1], ph, bl1);
                    mma16816(o[2*g],   pl, bh0);
                    mma16816(o[2*g+1], pl, bh1);
                }
            }
        }
    }

    // ---- epilogue ----
    float inv0 = 1.f / l0, inv1 = 1.f / l1;
    const int b_ = bh / HH, h_ = bh % HH;
    const size_t r0 = (size_t)(b_ * SS + qt * 128 + wid * 16 + (lane >> 2));
#pragma unroll
    for (int n = 0; n < 8; n++) {
        int d = h_ * 64 + n * 8 + (lane & 3) * 2;
        uint32_t hp, lp;
        split2(o[n][0] * inv0, o[n][1] * inv0, hp, lp);
        *(uint32_t*)&g_oh[r0 * DD + d] = hp;
        *(uint32_t*)&g_ol[r0 * DD + d] = lp;
        split2(o[n][2] * inv1, o[n][3] * inv1, hp, lp);
        *(uint32_t*)&g_oh[(r0 + 8) * DD + d] = hp;
        *(uint32_t*)&g_ol[(r0 + 8) * DD + d] = lp;
    }
}

// ---------------------------------------------------------------------------
extern "C" void kernel_launch(void* const* d_in, const int* in_sizes, int n_in,
                              void* d_out, int out_size)
{
    const float* x    = (const float*)d_in[0];
    const float* Wqkv = (const float*)d_in[1];
    const float* bqkv = (const float*)d_in[2];
    const float* Wout = (const float*)d_in[3];
    const float* bout = (const float*)d_in[4];
    float* out = (float*)d_out;

    cudaFuncSetAttribute(attn_mma_kernel, cudaFuncAttributeMaxDynamicSharedMemorySize, ATTN_SMEM);
    cudaFuncSetAttribute(gemm_qkv_tc, cudaFuncAttributeMaxDynamicSharedMemorySize, GEMM_SMEM);
    cudaFuncSetAttribute(gemm_out_tc, cudaFuncAttributeMaxDynamicSharedMemorySize, GEMM_SMEM);

    prep_kernel<<<PREP_CTAS, 256>>>(x, Wqkv, Wout);
    gemm_qkv_tc<<<dim3(N3 / 128, MM / 128), 512, GEMM_SMEM>>>(bqkv);
    attn_mma_kernel<<<dim3(SS / 128, BB * HH), 256, ATTN_SMEM>>>();
    gemm_out_tc<<<dim3(DD / 128, MM / 128), 512, GEMM_SMEM>>>(bout, out);
}

// round 17
// speedup vs baseline: 1.0537x; 1.0007x over previous
#include <cuda_runtime.h>
#include <cuda_bf16.h>
#include <cstdint>

#define BB 2
#define SS 4096
#define DD 768
#define HH 12
#define HD 64
#define N3 (3*DD)
#define MM (BB*SS)

// bf16 hi/lo scratch
__device__ __align__(16) __nv_bfloat16 g_qh[BB*HH*SS*HD], g_ql[BB*HH*SS*HD];
__device__ __align__(16) __nv_bfloat16 g_kh[BB*HH*SS*HD], g_kl[BB*HH*SS*HD];
__device__ __align__(16) __nv_bfloat16 g_vh[BB*HH*SS*HD], g_vl[BB*HH*SS*HD];
__device__ __align__(16) __nv_bfloat16 g_oh[MM*DD],  g_ol[MM*DD];
__device__ __align__(16) __nv_bfloat16 g_xh[MM*DD],  g_xl[MM*DD];
__device__ __align__(16) __nv_bfloat16 g_w1h[N3*DD], g_w1l[N3*DD];
__device__ __align__(16) __nv_bfloat16 g_w2h[DD*DD], g_w2l[DD*DD];

// ---------------- helpers ----------------
__device__ __forceinline__ uint32_t smem_u32(const void* p) {
    uint32_t a;
    asm("{ .reg .u64 t; cvta.to.shared.u64 t, %1; cvt.u32.u64 %0, t; }" : "=r"(a) : "l"(p));
    return a;
}
__device__ __forceinline__ void ldsm4(uint32_t* r, uint32_t addr) {
    asm volatile("ldmatrix.sync.aligned.m8n8.x4.shared.b16 {%0,%1,%2,%3}, [%4];"
        : "=r"(r[0]), "=r"(r[1]), "=r"(r[2]), "=r"(r[3]) : "r"(addr));
}
__device__ __forceinline__ void ldsm4t(uint32_t* r, uint32_t addr) {
    asm volatile("ldmatrix.sync.aligned.m8n8.x4.trans.shared.b16 {%0,%1,%2,%3}, [%4];"
        : "=r"(r[0]), "=r"(r[1]), "=r"(r[2]), "=r"(r[3]) : "r"(addr));
}
__device__ __forceinline__ void mma16816(float* c, const uint32_t* a, const uint32_t* b) {
    asm volatile(
        "mma.sync.aligned.m16n8k16.row.col.f32.bf16.bf16.f32 "
        "{%0,%1,%2,%3}, {%4,%5,%6,%7}, {%8,%9}, {%0,%1,%2,%3};"
        : "+f"(c[0]), "+f"(c[1]), "+f"(c[2]), "+f"(c[3])
        : "r"(a[0]), "r"(a[1]), "r"(a[2]), "r"(a[3]), "r"(b[0]), "r"(b[1]));
}
__device__ __forceinline__ uint32_t packbf(float x, float y) {
    __nv_bfloat162 h = __floats2bfloat162_rn(x, y);
    return *(uint32_t*)&h;
}
__device__ __forceinline__ void split2(float x, float y, uint32_t& h, uint32_t& l) {
    __nv_bfloat16 hx = __float2bfloat16(x), hy = __float2bfloat16(y);
    h = packbf(x, y);
    l = packbf(x - __bfloat162float(hx), y - __bfloat162float(hy));
}
#define CP_ASYNC16(dst, src) \
    asm volatile("cp.async.ca.shared.global [%0], [%1], 16;" :: "r"(dst), "l"(src))
#define CP_COMMIT() asm volatile("cp.async.commit_group;")
#define CP_WAIT(n)  asm volatile("cp.async.wait_group %0;" :: "n"(n))

// ---------------- GEMM smem layout: 3 cp.async stages (best measured) -------
#define TROW 80
#define BUF_B (128*TROW)
#define STAGE_B (4*BUF_B)
#define NSTG 3
#define OFF_BIAS (NSTG*STAGE_B)
#define GEMM_SMEM (OFF_BIAS + 512)
#define NCHUNK (DD/32)

// ---------------------------------------------------------------------------
// Fused prep kernel
// ---------------------------------------------------------------------------
#define PREP_SPLIT_CTAS (MM*DD/1024)          // 6144
#define PREP_T1_CTAS    ((N3/32)*(DD/32))     // 1728
#define PREP_T2_CTAS    ((DD/32)*(DD/32))     // 576
#define PREP_CTAS (PREP_SPLIT_CTAS + PREP_T1_CTAS + PREP_T2_CTAS)

__device__ __forceinline__ void transpose_split_body(
    const float* __restrict__ src, __nv_bfloat16* __restrict__ hi,
    __nv_bfloat16* __restrict__ lo, int R, int C, int bx, int by)
{
    __shared__ float t[32][33];
    int tx = threadIdx.x & 31, ty = threadIdx.x >> 5;
#pragma unroll
    for (int i = 0; i < 32; i += 8)
        t[ty + i][tx] = src[(size_t)(by + ty + i) * C + bx + tx];
    __syncthreads();
#pragma unroll
    for (int i = 0; i < 32; i += 8) {
        float v = t[tx][ty + i];
        __nv_bfloat16 h = __float2bfloat16(v);
        size_t o = (size_t)(bx + ty + i) * R + by + tx;
        hi[o] = h; lo[o] = __float2bfloat16(v - __bfloat162float(h));
    }
}

__global__ __launch_bounds__(256) void prep_kernel(
    const float* __restrict__ x, const float* __restrict__ Wqkv,
    const float* __restrict__ Wout)
{
    int b = blockIdx.x;
    if (b < PREP_SPLIT_CTAS) {
        int i = (b * 256 + threadIdx.x) * 4;
        float4 v = *(const float4*)(x + i);
        uint32_t h0, l0, h1, l1;
        split2(v.x, v.y, h0, l0);
        split2(v.z, v.w, h1, l1);
        *(uint32_t*)(g_xh + i) = h0; *(uint32_t*)(g_xh + i + 2) = h1;
        *(uint32_t*)(g_xl + i) = l0; *(uint32_t*)(g_xl + i + 2) = l1;
    } else if (b < PREP_SPLIT_CTAS + PREP_T1_CTAS) {
        int bb = b - PREP_SPLIT_CTAS;
        int bx = (bb % (N3/32)) * 32, by = (bb / (N3/32)) * 32;
        transpose_split_body(Wqkv, g_w1h, g_w1l, DD, N3, bx, by);
    } else {
        int bb = b - PREP_SPLIT_CTAS - PREP_T1_CTAS;
        int bx = (bb % (DD/32)) * 32, by = (bb / (DD/32)) * 32;
        transpose_split_body(Wout, g_w2h, g_w2l, DD, DD, bx, by);
    }
}

// ---------------------------------------------------------------------------
// bf16x3 MMA mainloop (round-16 proven)
// ---------------------------------------------------------------------------
__device__ __forceinline__ void gemm_mainloop(
    const __nv_bfloat16* __restrict__ Ah, const __nv_bfloat16* __restrict__ Al,
    const __nv_bfloat16* __restrict__ Bh, const __nv_bfloat16* __restrict__ Bl,
    const float* __restrict__ bias_g,
    char* sm, uint32_t smb, int row0, int col0, float c[2][4][4])
{
    const int tid  = threadIdx.x;
    const int wid  = tid >> 5, lane = tid & 31;
    const int wr   = wid >> 2, wc = wid & 3;

    if (tid < 128) ((float*)(sm + OFF_BIAS))[tid] = bias_g[col0 + tid];

    const int crow = tid >> 2;
    const int ck8  = (tid & 3) * 8;
    const __nv_bfloat16* gA_h = Ah + (size_t)(row0 + crow) * DD + ck8;
    const __nv_bfloat16* gA_l = Al + (size_t)(row0 + crow) * DD + ck8;
    const __nv_bfloat16* gB_h = Bh + (size_t)(col0 + crow) * DD + ck8;
    const __nv_bfloat16* gB_l = Bl + (size_t)(col0 + crow) * DD + ck8;
    const uint32_t sdst = smb + (uint32_t)(crow * TROW + ck8 * 2);

#pragma unroll
    for (int p = 0; p < 2; p++) {
        const uint32_t so = sdst + (uint32_t)p * STAGE_B;
        const int ko = p * 32;
        CP_ASYNC16(so,             gA_h + ko);
        CP_ASYNC16(so + BUF_B,     gA_l + ko);
        CP_ASYNC16(so + 2*BUF_B,   gB_h + ko);
        CP_ASYNC16(so + 3*BUF_B,   gB_l + ko);
        CP_COMMIT();
    }

    const int lrow = lane & 15;
    const int lk   = (lane >> 4) * 8;

    int st = 0;
    for (int ch = 0; ch < NCHUNK; ch++) {
        {
            int nx = ch + 2;
            if (nx < NCHUNK) {
                int stn = st + 2; if (stn >= NSTG) stn -= NSTG;
                const uint32_t so = sdst + (uint32_t)stn * STAGE_B;
                const int ko = nx * 32;
                CP_ASYNC16(so,           gA_h + ko);
                CP_ASYNC16(so + BUF_B,   gA_l + ko);
                CP_ASYNC16(so + 2*BUF_B, gB_h + ko);
                CP_ASYNC16(so + 3*BUF_B, gB_l + ko);
            }
            CP_COMMIT();
        }
        CP_WAIT(2);
        __syncthreads();

        const uint32_t stg = smb + (uint32_t)st * STAGE_B;

        uint32_t a_hi[2][2][4], a_lo[2][2][4], b_hi[2][4][2], b_lo[2][4][2];
#pragma unroll
        for (int ks = 0; ks < 2; ks++) {
            const uint32_t kb = (uint32_t)((ks * 16 + lk) * 2);
#pragma unroll
            for (int mt = 0; mt < 2; mt++) {
                uint32_t ra = stg + (uint32_t)((wr * 32 + mt * 16 + lrow) * TROW) + kb;
                ldsm4(a_hi[ks][mt], ra);
                ldsm4(a_lo[ks][mt], ra + BUF_B);
            }
#pragma unroll
            for (int g = 0; g < 2; g++) {
                uint32_t rb = stg + (uint32_t)((wc * 32 + g * 16 + lrow) * TROW) + kb;
                uint32_t r[4];
                ldsm4(r, rb + 2*BUF_B);
                b_hi[ks][2*g][0] = r[0]; b_hi[ks][2*g][1] = r[2];
                b_hi[ks][2*g+1][0] = r[1]; b_hi[ks][2*g+1][1] = r[3];
                ldsm4(r, rb + 3*BUF_B);
                b_lo[ks][2*g][0] = r[0]; b_lo[ks][2*g][1] = r[2];
                b_lo[ks][2*g+1][0] = r[1]; b_lo[ks][2*g+1][1] = r[3];
            }
        }
#pragma unroll
        for (int ks = 0; ks < 2; ks++) {
#pragma unroll
            for (int mt = 0; mt < 2; mt++)
#pragma unroll
                for (int nt = 0; nt < 4; nt++)
                    mma16816(c[mt][nt], a_hi[ks][mt], b_hi[ks][nt]);
#pragma unroll
            for (int mt = 0; mt < 2; mt++)
#pragma unroll
                for (int nt = 0; nt < 4; nt++)
                    mma16816(c[mt][nt], a_hi[ks][mt], b_lo[ks][nt]);
#pragma unroll
            for (int mt = 0; mt < 2; mt++)
#pragma unroll
                for (int nt = 0; nt < 4; nt++)
                    mma16816(c[mt][nt], a_lo[ks][mt], b_hi[ks][nt]);
        }
        st++; if (st >= NSTG) st = 0;
    }
    __syncthreads();
}

// ---------------------------------------------------------------------------
// GEMM1: qkv projection -> bf16 hi/lo Q(scaled incl. log2e)/K/V in [b,h,s,d]
// ---------------------------------------------------------------------------
__global__ __launch_bounds__(512) void gemm_qkv_tc(const float* __restrict__ bqkv)
{
    extern __shared__ char sm[];
    const uint32_t smb = smem_u32(sm);
    const int col0 = blockIdx.x * 128;
    const int row0 = blockIdx.y * 128;
    const int tid = threadIdx.x, wid = tid >> 5, lane = tid & 31;
    const int wr = wid >> 2, wc = wid & 3;

    float c[2][4][4] = {};
    gemm_mainloop(g_xh, g_xl, g_w1h, g_w1l, bqkv, sm, smb, row0, col0, c);

    const float* bias_s = (const float*)(sm + OFF_BIAS);
    const int which = col0 / DD;
    const int h0 = (col0 % DD) / HD;
    const int b_ = row0 >> 12;
    const int s0 = row0 & 4095;
    const float scale = (which == 0) ? 0.125f * 1.44269504088896f : 1.0f;

    __nv_bfloat16* dh = (which == 0) ? g_qh : (which == 1) ? g_kh : g_vh;
    __nv_bfloat16* dl = (which == 0) ? g_ql : (which == 1) ? g_kl : g_vl;

#pragma unroll
    for (int mt = 0; mt < 2; mt++)
#pragma unroll
        for (int nt = 0; nt < 4; nt++) {
            int cl = wc * 32 + nt * 8 + (lane & 3) * 2;
            int h  = h0 + (cl >> 6);
            int d  = cl & 63;
            float bx = bias_s[cl], by = bias_s[cl + 1];
            const size_t base = (size_t)(b_ * HH + h) * SS * HD;
#pragma unroll
            for (int hh = 0; hh < 2; hh++) {
                int gs = s0 + wr * 32 + mt * 16 + (lane >> 2) + hh * 8;
                float v0 = (c[mt][nt][2*hh]   + bx) * scale;
                float v1 = (c[mt][nt][2*hh+1] + by) * scale;
                uint32_t hp, lp;
                split2(v0, v1, hp, lp);
                *(uint32_t*)&dh[base + (size_t)gs * HD + d] = hp;
                *(uint32_t*)&dl[base + (size_t)gs * HD + d] = lp;
            }
        }
}

// ---------------------------------------------------------------------------
// GEMM2: out projection
// ---------------------------------------------------------------------------
__global__ __launch_bounds__(512) void gemm_out_tc(const float* __restrict__ bout,
                                                   float* __restrict__ Y)
{
    extern __shared__ char sm[];
    const uint32_t smb = smem_u32(sm);
    const int col0 = blockIdx.x * 128;
    const int row0 = blockIdx.y * 128;
    const int tid = threadIdx.x, wid = tid >> 5, lane = tid & 31;
    const int wr = wid >> 2, wc = wid & 3;

    float c[2][4][4] = {};
    gemm_mainloop(g_oh, g_ol, g_w2h, g_w2l, bout, sm, smb, row0, col0, c);

    const float* bias_s = (const float*)(sm + OFF_BIAS);
#pragma unroll
    for (int mt = 0; mt < 2; mt++)
#pragma unroll
        for (int nt = 0; nt < 4; nt++) {
            int cl = wc * 32 + nt * 8 + (lane & 3) * 2;
            float bx = bias_s[cl], by = bias_s[cl + 1];
#pragma unroll
            for (int hh = 0; hh < 2; hh++) {
                int r = row0 + wr * 32 + mt * 16 + (lane >> 2) + hh * 8;
                float2 v = make_float2(c[mt][nt][2*hh] + bx, c[mt][nt][2*hh+1] + by);
                *(float2*)&Y[(size_t)r * DD + col0 + cl] = v;
            }
        }
}

// ---------------------------------------------------------------------------
// Flash attention: 128-thread CTAs over 64-query tiles (3 CTAs/SM target),
// deferred 128-key softmax (exp2), 2 KV buffers, register prefetch.
// Per-warp structure identical to the proven 906us kernel.
// ---------------------------------------------------------------------------
#define KST 72
#define KBYTES (64*KST*2)            // 9216 per operand buffer
#define QBYTES (64*KST*2)            // 9216 per Q hi/lo (64 rows now)
#define ABUF (4*KBYTES)              // 36864 per KV tile buffer
#define ATTN_SMEM (2*ABUF)           // 73728

__global__ __launch_bounds__(128) void attn_mma_kernel()
{
    extern __shared__ char smc[];
    const uint32_t smb = smem_u32(smc);
    const int qt  = gridDim.x - 1 - blockIdx.x;    // 64-row tile, heavy first
    const int bh  = blockIdx.y;
    const int tid = threadIdx.x;
    const int wid = tid >> 5, lane = tid & 31;
    const int lrow = lane & 15, lk = (lane >> 4) * 8;

    const size_t bhoff = (size_t)bh * SS * HD;
    const __nv_bfloat16* Qhg = g_qh + bhoff;
    const __nv_bfloat16* Qlg = g_ql + bhoff;
    const __nv_bfloat16* Khg = g_kh + bhoff;
    const __nv_bfloat16* Klg = g_kl + bhoff;
    const __nv_bfloat16* Vhg = g_vh + bhoff;
    const __nv_bfloat16* Vlg = g_vl + bhoff;

    // ---- Q stage (64 rows) ----
    {
        __nv_bfloat16* qs = (__nv_bfloat16*)smc;
#pragma unroll
        for (int i = 0; i < 4; i++) {
            int f = tid + i * 128;                 // 0..511
            int r = f >> 3, c8 = (f & 7) * 8;
            *(uint4*)&qs[r * KST + c8] =
                *(const uint4*)&Qhg[(size_t)(qt * 64 + r) * HD + c8];
            *(uint4*)&qs[64 * KST + r * KST + c8] =
                *(const uint4*)&Qlg[(size_t)(qt * 64 + r) * HD + c8];
        }
    }
    __syncthreads();

    uint32_t qh[4][4], ql[4][4];
#pragma unroll
    for (int t = 0; t < 4; t++) {
        uint32_t a = smb + (uint32_t)((wid * 16 + lrow) * KST + t * 16 + lk) * 2;
        ldsm4(qh[t], a);
        ldsm4(ql[t], a + QBYTES);
    }

    float o[8][4] = {};
    float m0 = -1e30f, m1 = -1e30f, l0 = 0.f, l1 = 0.f;

    const int np = (qt + 2) >> 1;    // number of 128-key pairs (tail over-covered, masked)

    uint4 pk[4][4];
#pragma unroll
    for (int i = 0; i < 4; i++) {
        int f = tid + i * 128;
        int r = f >> 3, c8 = (f & 7) * 8;
        size_t go = (size_t)r * HD + c8;
        pk[i][0] = *(const uint4*)&Khg[go];
        pk[i][1] = *(const uint4*)&Klg[go];
        pk[i][2] = *(const uint4*)&Vhg[go];
        pk[i][3] = *(const uint4*)&Vlg[go];
    }

    for (int p = 0; p < np; p++) {
        float s0[8][4] = {}, s1[8][4] = {};

        // ===== phase A: tile 2p -> buf0 =====
        __syncthreads();
        {
            __nv_bfloat16* ks = (__nv_bfloat16*)smc;
#pragma unroll
            for (int i = 0; i < 4; i++) {
                int f = tid + i * 128;
                int r = f >> 3, c8 = (f & 7) * 8;
                int so = r * KST + c8;
                *(uint4*)&ks[so]            = pk[i][0];
                *(uint4*)&ks[64*KST   + so] = pk[i][1];
                *(uint4*)&ks[2*64*KST + so] = pk[i][2];
                *(uint4*)&ks[3*64*KST + so] = pk[i][3];
            }
        }
        __syncthreads();

#pragma unroll
        for (int i = 0; i < 4; i++) {
            int f = tid + i * 128;
            int r = f >> 3, c8 = (f & 7) * 8;
            size_t go = (size_t)((2 * p + 1) * 64 + r) * HD + c8;
            pk[i][0] = *(const uint4*)&Khg[go];
            pk[i][1] = *(const uint4*)&Klg[go];
            pk[i][2] = *(const uint4*)&Vhg[go];
            pk[i][3] = *(const uint4*)&Vlg[go];
        }

#pragma unroll
        for (int t = 0; t < 4; t++) {
#pragma unroll
            for (int g = 0; g < 4; g++) {
                uint32_t a = smb + (uint32_t)((g * 16 + lrow) * KST + t * 16 + lk) * 2;
                uint32_t rh[4], rl[4];
                ldsm4(rh, a);
                ldsm4(rl, a + KBYTES);
                uint32_t bh0[2] = {rh[0], rh[2]}, bh1[2] = {rh[1], rh[3]};
                uint32_t bl0[2] = {rl[0], rl[2]}, bl1[2] = {rl[1], rl[3]};
                mma16816(s0[2*g],   qh[t], bh0);
                mma16816(s0[2*g+1], qh[t], bh1);
                mma16816(s0[2*g],   qh[t], bl0);
                mma16816(s0[2*g+1], qh[t], bl1);
                mma16816(s0[2*g],   ql[t], bh0);
                mma16816(s0[2*g+1], ql[t], bh1);
            }
        }

        // ===== phase B: tile 2p+1 -> buf1 =====
        {
            __nv_bfloat16* ks = (__nv_bfloat16*)(smc + ABUF);
#pragma unroll
            for (int i = 0; i < 4; i++) {
                int f = tid + i * 128;
                int r = f >> 3, c8 = (f & 7) * 8;
                int so = r * KST + c8;
                *(uint4*)&ks[so]            = pk[i][0];
                *(uint4*)&ks[64*KST   + so] = pk[i][1];
                *(uint4*)&ks[2*64*KST + so] = pk[i][2];
                *(uint4*)&ks[3*64*KST + so] = pk[i][3];
            }
        }
        __syncthreads();

        if (p + 1 < np) {
#pragma unroll
            for (int i = 0; i < 4; i++) {
                int f = tid + i * 128;
                int r = f >> 3, c8 = (f & 7) * 8;
                size_t go = (size_t)((2 * p + 2) * 64 + r) * HD + c8;
                pk[i][0] = *(const uint4*)&Khg[go];
                pk[i][1] = *(const uint4*)&Klg[go];
                pk[i][2] = *(const uint4*)&Vhg[go];
                pk[i][3] = *(const uint4*)&Vlg[go];
            }
        }

#pragma unroll
        for (int t = 0; t < 4; t++) {
#pragma unroll
            for (int g = 0; g < 4; g++) {
                uint32_t a = smb + (uint32_t)ABUF +
                             (uint32_t)((g * 16 + lrow) * KST + t * 16 + lk) * 2;
                uint32_t rh[4], rl[4];
                ldsm4(rh, a);
                ldsm4(rl, a + KBYTES);
                uint32_t bh0[2] = {rh[0], rh[2]}, bh1[2] = {rh[1], rh[3]};
                uint32_t bl0[2] = {rl[0], rl[2]}, bl1[2] = {rl[1], rl[3]};
                mma16816(s1[2*g],   qh[t], bh0);
                mma16816(s1[2*g+1], qh[t], bh1);
                mma16816(s1[2*g],   qh[t], bl0);
                mma16816(s1[2*g+1], qh[t], bl1);
                mma16816(s1[2*g],   ql[t], bh0);
                mma16816(s1[2*g+1], ql[t], bh1);
            }
        }

        // ===== causal mask (last pair only; covers over-shot tail tile) =====
        if (p == np - 1) {
            int rbase = qt * 64 + wid * 16 + (lane >> 2);
            int cb0 = 2 * p * 64 + (lane & 3) * 2;
#pragma unroll
            for (int n = 0; n < 8; n++) {
                int cc = cb0 + n * 8;
                if (cc      > rbase)     s0[n][0] = -1e30f;
                if (cc + 1  > rbase)     s0[n][1] = -1e30f;
                if (cc      > rbase + 8) s0[n][2] = -1e30f;
                if (cc + 1  > rbase + 8) s0[n][3] = -1e30f;
                int cd = cc + 64;
                if (cd      > rbase)     s1[n][0] = -1e30f;
                if (cd + 1  > rbase)     s1[n][1] = -1e30f;
                if (cd      > rbase + 8) s1[n][2] = -1e30f;
                if (cd + 1  > rbase + 8) s1[n][3] = -1e30f;
            }
        }

        // ===== single online-softmax round over 128 keys (base-2) =====
        float mx0 = -1e30f, mx1 = -1e30f;
#pragma unroll
        for (int n = 0; n < 8; n++) {
            mx0 = fmaxf(mx0, fmaxf(fmaxf(s0[n][0], s0[n][1]), fmaxf(s1[n][0], s1[n][1])));
            mx1 = fmaxf(mx1, fmaxf(fmaxf(s0[n][2], s0[n][3]), fmaxf(s1[n][2], s1[n][3])));
        }
        mx0 = fmaxf(mx0, __shfl_xor_sync(0xffffffffu, mx0, 1));
        mx0 = fmaxf(mx0, __shfl_xor_sync(0xffffffffu, mx0, 2));
        mx1 = fmaxf(mx1, __shfl_xor_sync(0xffffffffu, mx1, 1));
        mx1 = fmaxf(mx1, __shfl_xor_sync(0xffffffffu, mx1, 2));
        float mn0 = fmaxf(m0, mx0), mn1 = fmaxf(m1, mx1);
        float a0 = exp2f(m0 - mn0), a1 = exp2f(m1 - mn1);
        m0 = mn0; m1 = mn1;
        float lt0 = 0.f, lt1 = 0.f;
#pragma unroll
        for (int n = 0; n < 8; n++) {
            s0[n][0] = exp2f(s0[n][0] - mn0); lt0 += s0[n][0];
            s0[n][1] = exp2f(s0[n][1] - mn0); lt0 += s0[n][1];
            s0[n][2] = exp2f(s0[n][2] - mn1); lt1 += s0[n][2];
            s0[n][3] = exp2f(s0[n][3] - mn1); lt1 += s0[n][3];
            s1[n][0] = exp2f(s1[n][0] - mn0); lt0 += s1[n][0];
            s1[n][1] = exp2f(s1[n][1] - mn0); lt0 += s1[n][1];
            s1[n][2] = exp2f(s1[n][2] - mn1); lt1 += s1[n][2];
            s1[n][3] = exp2f(s1[n][3] - mn1); lt1 += s1[n][3];
        }
        lt0 += __shfl_xor_sync(0xffffffffu, lt0, 1);
        lt0 += __shfl_xor_sync(0xffffffffu, lt0, 2);
        lt1 += __shfl_xor_sync(0xffffffffu, lt1, 1);
        lt1 += __shfl_xor_sync(0xffffffffu, lt1, 2);
        l0 = l0 * a0 + lt0;
        l1 = l1 * a1 + lt1;
#pragma unroll
        for (int n = 0; n < 8; n++) {
            o[n][0] *= a0; o[n][1] *= a0; o[n][2] *= a1; o[n][3] *= a1;
        }

        // ===== O += P0 V0 + P1 V1 =====
#pragma unroll
        for (int half = 0; half < 2; half++) {
            float (*sp)[4] = half ? s1 : s0;
            const uint32_t vbase = smb + (uint32_t)(half * ABUF) + (uint32_t)(2*KBYTES);
#pragma unroll
            for (int t = 0; t < 4; t++) {
                uint32_t ph[4], pl[4];
                split2(sp[2*t][0],   sp[2*t][1],   ph[0], pl[0]);
                split2(sp[2*t][2],   sp[2*t][3],   ph[1], pl[1]);
                split2(sp[2*t+1][0], sp[2*t+1][1], ph[2], pl[2]);
                split2(sp[2*t+1][2], sp[2*t+1][3], ph[3], pl[3]);
#pragma unroll
                for (int g = 0; g < 4; g++) {
                    uint32_t a = vbase +
                                 (uint32_t)((t * 16 + lrow) * KST + g * 16 + lk) * 2;
                    uint32_t rh[4], rl[4];
                    ldsm4t(rh, a);
                    ldsm4t(rl, a + KBYTES);
                    uint32_t bh0[2] = {rh[0], rh[1]}, bh1[2] = {rh[2], rh[3]};
                    uint32_t bl0[2] = {rl[0], rl[1]}, bl1[2] = {rl[2], rl[3]};
                    mma16816(o[2*g],   ph, bh0);
                    mma16816(o[2*g+1], ph, bh1);
                    mma16816(o[2*g],   ph, bl0);
                    mma16816(o[2*g+1], ph, bl1);
                    mma16816(o[2*g],   pl, bh0);
                    mma16816(o[2*g+1], pl, bh1);
                }
            }
        }
    }

    // ---- epilogue ----
    float inv0 = 1.f / l0, inv1 = 1.f / l1;
    const int b_ = bh / HH, h_ = bh % HH;
    const size_t r0 = (size_t)(b_ * SS + qt * 64 + wid * 16 + (lane >> 2));
#pragma unroll
    for (int n = 0; n < 8; n++) {
        int d = h_ * 64 + n * 8 + (lane & 3) * 2;
        uint32_t hp, lp;
        split2(o[n][0] * inv0, o[n][1] * inv0, hp, lp);
        *(uint32_t*)&g_oh[r0 * DD + d] = hp;
        *(uint32_t*)&g_ol[r0 * DD + d] = lp;
        split2(o[n][2] * inv1, o[n][3] * inv1, hp, lp);
        *(uint32_t*)&g_oh[(r0 + 8) * DD + d] = hp;
        *(uint32_t*)&g_ol[(r0 + 8) * DD + d] = lp;
    }
}

// ---------------------------------------------------------------------------
extern "C" void kernel_launch(void* const* d_in, const int* in_sizes, int n_in,
                              void* d_out, int out_size)
{
    const float* x    = (const float*)d_in[0];
    const float* Wqkv = (const float*)d_in[1];
    const float* bqkv = (const float*)d_in[2];
    const float* Wout = (const float*)d_in[3];
    const float* bout = (const float*)d_in[4];
    float* out = (float*)d_out;

    cudaFuncSetAttribute(attn_mma_kernel, cudaFuncAttributeMaxDynamicSharedMemorySize, ATTN_SMEM);
    cudaFuncSetAttribute(gemm_qkv_tc, cudaFuncAttributeMaxDynamicSharedMemorySize, GEMM_SMEM);
    cudaFuncSetAttribute(gemm_out_tc, cudaFuncAttributeMaxDynamicSharedMemorySize, GEMM_SMEM);

    prep_kernel<<<PREP_CTAS, 256>>>(x, Wqkv, Wout);
    gemm_qkv_tc<<<dim3(N3 / 128, MM / 128), 512, GEMM_SMEM>>>(bqkv);
    attn_mma_kernel<<<dim3(SS / 64, BB * HH), 128, ATTN_SMEM>>>();
    gemm_out_tc<<<dim3(DD / 128, MM / 128), 512, GEMM_SMEM>>>(bout, out);
}